// round 2
// baseline (speedup 1.0000x reference)
#include <cuda_runtime.h>

#define BB 8
#define KK 5
#define TT 40
#define VV 32000
#define EE 256
#define HH 512
#define AA 512
#define GG (KK*BB)      /* 40 rows (beam-major: g = k*BB + b) */
#define G3 (3*HH)       /* 1536 gate outputs */
#define NEGF (-1e9f)

#define VT 128          /* vocab tile per block */
#define NBLK (VV/VT)    /* 250 */
#define JT 128          /* gate tile per block  */

// ---------------- persistent device state ----------------
__device__ float g_hn[2][GG*HH];          // ping-pong hidden (raw hn rows, pre-reorder)
__device__ float g_gi[GG*G3];
__device__ float g_gh[GG*G3];
__device__ float g_bp[GG];                // beam scores  [k*BB+b]
__device__ int   g_sel_org[GG];           // origin slot to gather prev hn  [k*BB+b]
__device__ int   g_sel_tok[GG];           // token to embed this step       [k*BB+b]
__device__ int   g_org_all[TT*BB*KK];
__device__ int   g_tok_all[TT*BB*KK];
__device__ float g_out_all[(size_t)TT*KK*BB*VV];   // raw logits per step, 204.8 MB scratch
__device__ float g_part_v[NBLK*GG*5];
__device__ int   g_part_i[NBLK*GG*5];
__device__ float g_part_m[NBLK*GG];
__device__ float g_part_s[NBLK*GG];
__device__ int   g_bt_slot[BB*KK*TT];
__device__ int   g_bt_tok [BB*KK*TT];

// comparator matching jax.lax.top_k tie-break: higher value wins, ties -> lower index
__device__ __forceinline__ bool better(float av, int ai, float bv, int bi) {
    return (av > bv) || (av == bv && ai < bi);
}

// ---------------- init: h0 = attrs @ Wt^T + bt, beam state ----------------
__global__ void k_init(const float* __restrict__ attrs, const float* __restrict__ tw,
                       const float* __restrict__ tb, const int* __restrict__ bosp) {
    __shared__ float sa[AA];
    int b = blockIdx.x;
    for (int i = threadIdx.x; i < AA; i += blockDim.x) sa[i] = attrs[b*AA + i];
    __syncthreads();
    for (int j = threadIdx.x; j < HH; j += blockDim.x) {
        const float* w = &tw[(size_t)j*AA];
        float acc = 0.f;
        for (int a = 0; a < AA; a++) acc += sa[a] * w[a];
        acc += tb[j];
        for (int k = 0; k < KK; k++) g_hn[0][(k*BB + b)*HH + j] = acc;
    }
    if (b == 0 && threadIdx.x < GG) {
        int i = threadIdx.x;
        int k = i / BB;
        g_bp[i]      = (k == 0) ? 0.f : NEGF;
        g_sel_org[i] = k;           // initial hidden identical across beams
        g_sel_tok[i] = bosp[0];
    }
}

// ---------------- GRU gate GEMMs: gi = x@Wih^T + bih ; gh = h@Whh^T + bhh ----------------
__global__ __launch_bounds__(256)
void k_gru_gemm(const float* __restrict__ emb,
                const float* __restrict__ w_ih, const float* __restrict__ b_ih,
                const float* __restrict__ w_hh, const float* __restrict__ b_hh,
                int prev) {
    const int mode = blockIdx.z;                  // 0: gi (input E=256), 1: gh (hidden H=512)
    const int KIN  = mode ? HH : EE;
    const float* __restrict__ W    = mode ? w_hh : w_ih;
    const float* __restrict__ bias = mode ? b_hh : b_ih;
    float* __restrict__ OUT        = mode ? g_gh : g_gi;

    __shared__ float wt[64][JT + 1];              // transposed weight tile
    __shared__ float it[GG * 64];                 // input tile (rows x 64)

    int tid = threadIdx.x, tx = tid & 31, ty = tid >> 5;
    int j0 = blockIdx.x * JT;
    float acc[4][5] = {};

    const int nchunk = KIN / 64;
    for (int c = 0; c < nchunk; c++) {
        int kk0 = c * 64;
        for (int idx = tid; idx < JT*16; idx += 256) {
            int jl = idx >> 4, q = idx & 15;
            float4 w4 = *reinterpret_cast<const float4*>(&W[(size_t)(j0 + jl)*KIN + kk0 + q*4]);
            wt[q*4+0][jl] = w4.x; wt[q*4+1][jl] = w4.y;
            wt[q*4+2][jl] = w4.z; wt[q*4+3][jl] = w4.w;
        }
        for (int idx = tid; idx < GG*16; idx += 256) {
            int g = idx >> 4, q = idx & 15;
            const float* src;
            if (mode == 0) src = &emb[(size_t)g_sel_tok[g] * EE];
            else { int b = g % BB; src = &g_hn[prev][(g_sel_org[g]*BB + b)*HH]; }
            *reinterpret_cast<float4*>(&it[g*64 + q*4]) =
                *reinterpret_cast<const float4*>(&src[kk0 + q*4]);
        }
        __syncthreads();
        for (int kk = 0; kk < 64; kk++) {
            float wv[4];
            #pragma unroll
            for (int i = 0; i < 4; i++) wv[i] = wt[kk][i*32 + tx];
            #pragma unroll
            for (int r = 0; r < 5; r++) {
                float xv = it[(ty + 8*r)*64 + kk];
                #pragma unroll
                for (int i = 0; i < 4; i++) acc[i][r] += wv[i] * xv;
            }
        }
        __syncthreads();
    }
    #pragma unroll
    for (int r = 0; r < 5; r++) {
        int g = ty + 8*r;
        #pragma unroll
        for (int i = 0; i < 4; i++) {
            int j = j0 + i*32 + tx;
            OUT[(size_t)g*G3 + j] = acc[i][r] + bias[j];
        }
    }
}

// ---------------- GRU elementwise gates ----------------
__global__ void k_gru_gates(int prev, int cur) {
    int idx = blockIdx.x * blockDim.x + threadIdx.x;
    if (idx >= GG*HH) return;
    int g = idx / HH, j = idx % HH, b = g % BB;
    float gi_r = g_gi[(size_t)g*G3 + j],        gh_r = g_gh[(size_t)g*G3 + j];
    float gi_z = g_gi[(size_t)g*G3 + HH + j],   gh_z = g_gh[(size_t)g*G3 + HH + j];
    float gi_n = g_gi[(size_t)g*G3 + 2*HH + j], gh_n = g_gh[(size_t)g*G3 + 2*HH + j];
    float hprev = g_hn[prev][(g_sel_org[g]*BB + b)*HH + j];
    float r = 1.f / (1.f + expf(-(gi_r + gh_r)));
    float z = 1.f / (1.f + expf(-(gi_z + gh_z)));
    float n = tanhf(gi_n + r*gh_n);
    g_hn[cur][g*HH + j] = (1.f - z)*n + z*hprev;
}

// ---------------- vocab projection + per-block partial (max, sumexp, top5) ----------------
__global__ __launch_bounds__(256)
void k_linear(const float* __restrict__ lw, const float* __restrict__ lb, int t, int cur) {
    __shared__ float wt[64][VT + 1];
    __shared__ float it[GG * 64];

    int tid = threadIdx.x, tx = tid & 31, ty = tid >> 5;
    int v0 = blockIdx.x * VT;
    float acc[4][5] = {};

    for (int c = 0; c < HH/64; c++) {
        int kk0 = c * 64;
        for (int idx = tid; idx < VT*16; idx += 256) {
            int vl = idx >> 4, q = idx & 15;
            float4 w4 = *reinterpret_cast<const float4*>(&lw[(size_t)(v0 + vl)*HH + kk0 + q*4]);
            wt[q*4+0][vl] = w4.x; wt[q*4+1][vl] = w4.y;
            wt[q*4+2][vl] = w4.z; wt[q*4+3][vl] = w4.w;
        }
        for (int idx = tid; idx < GG*16; idx += 256) {
            int g = idx >> 4, q = idx & 15;
            *reinterpret_cast<float4*>(&it[g*64 + q*4]) =
                *reinterpret_cast<const float4*>(&g_hn[cur][g*HH + kk0 + q*4]);
        }
        __syncthreads();
        for (int kk = 0; kk < 64; kk++) {
            float wv[4];
            #pragma unroll
            for (int i = 0; i < 4; i++) wv[i] = wt[kk][i*32 + tx];
            #pragma unroll
            for (int r = 0; r < 5; r++) {
                float xv = it[(ty + 8*r)*64 + kk];
                #pragma unroll
                for (int i = 0; i < 4; i++) acc[i][r] += wv[i] * xv;
            }
        }
        __syncthreads();
    }

    // bias + store raw logits
    #pragma unroll
    for (int i = 0; i < 4; i++) {
        float bias = lb[v0 + i*32 + tx];
        #pragma unroll
        for (int r = 0; r < 5; r++) acc[i][r] += bias;
    }
    #pragma unroll
    for (int r = 0; r < 5; r++) {
        int g = ty + 8*r, k = g / BB, b = g % BB;
        float* dst = &g_out_all[(((size_t)t*KK + k)*BB + b)*VV];
        #pragma unroll
        for (int i = 0; i < 4; i++) dst[v0 + i*32 + tx] = acc[i][r];
    }

    // per-row (per-warp) partials over this 128-vocab tile
    #pragma unroll
    for (int r = 0; r < 5; r++) {
        int g = ty + 8*r;
        float lm = fmaxf(fmaxf(acc[0][r], acc[1][r]), fmaxf(acc[2][r], acc[3][r]));
        for (int off = 16; off; off >>= 1) lm = fmaxf(lm, __shfl_xor_sync(0xffffffffu, lm, off));
        float ls = 0.f;
        #pragma unroll
        for (int i = 0; i < 4; i++) ls += expf(acc[i][r] - lm);
        for (int off = 16; off; off >>= 1) ls += __shfl_xor_sync(0xffffffffu, ls, off);

        float cv[4]; int ci[4];
        #pragma unroll
        for (int i = 0; i < 4; i++) { cv[i] = acc[i][r]; ci[i] = v0 + i*32 + tx; }
        for (int s = 0; s < 5; s++) {
            float bv = cv[0]; int bi = ci[0], bsl = 0;
            #pragma unroll
            for (int i = 1; i < 4; i++)
                if (better(cv[i], ci[i], bv, bi)) { bv = cv[i]; bi = ci[i]; bsl = i; }
            float wv2 = bv; int wi2 = bi;
            for (int off = 16; off; off >>= 1) {
                float ov = __shfl_xor_sync(0xffffffffu, wv2, off);
                int   oi = __shfl_xor_sync(0xffffffffu, wi2, off);
                if (better(ov, oi, wv2, wi2)) { wv2 = ov; wi2 = oi; }
            }
            if (tx == 0) {
                g_part_v[((size_t)blockIdx.x*GG + g)*5 + s] = wv2;
                g_part_i[((size_t)blockIdx.x*GG + g)*5 + s] = wi2;
            }
            if (wi2 == bi) cv[bsl] = -1e38f;   // vocab idx unique -> unique owner
        }
        if (tx == 0) {
            g_part_m[blockIdx.x*GG + g] = lm;
            g_part_s[blockIdx.x*GG + g] = ls;
        }
    }
}

// ---------------- cross-block reduce + beam combine/select (per batch) ----------------
__global__ void k_reduce_select(int t) {
    int b = blockIdx.x;
    int tid = threadIdx.x, tx = tid & 31, w = tid >> 5;
    __shared__ float s_tv[KK][5];
    __shared__ int   s_ti[KK][5];
    __shared__ float s_lse[KK];

    if (w < KK) {
        int g = w*BB + b;
        // logsumexp merge
        float m = -1e38f;
        for (int p = tx; p < NBLK; p += 32) m = fmaxf(m, g_part_m[p*GG + g]);
        for (int off = 16; off; off >>= 1) m = fmaxf(m, __shfl_xor_sync(0xffffffffu, m, off));
        float s = 0.f;
        for (int p = tx; p < NBLK; p += 32)
            s += g_part_s[p*GG + g] * expf(g_part_m[p*GG + g] - m);
        for (int off = 16; off; off >>= 1) s += __shfl_xor_sync(0xffffffffu, s, off);

        // streaming per-lane top5 over 250*5 candidates
        float tv[5]; int ti[5];
        #pragma unroll
        for (int i = 0; i < 5; i++) { tv[i] = -1e38f; ti[i] = 0x7fffffff; }
        for (int p = tx; p < NBLK; p += 32) {
            #pragma unroll
            for (int q = 0; q < 5; q++) {
                float v = g_part_v[((size_t)p*GG + g)*5 + q];
                int  id = g_part_i[((size_t)p*GG + g)*5 + q];
                if (better(v, id, tv[4], ti[4])) {
                    tv[4] = v; ti[4] = id;
                    #pragma unroll
                    for (int j = 4; j > 0; j--)
                        if (better(tv[j], ti[j], tv[j-1], ti[j-1])) {
                            float fv = tv[j]; tv[j] = tv[j-1]; tv[j-1] = fv;
                            int   fi = ti[j]; ti[j] = ti[j-1]; ti[j-1] = fi;
                        }
                }
            }
        }
        int hp = 0;
        for (int s5 = 0; s5 < 5; s5++) {
            float bv = (hp < 5) ? tv[hp] : -1e38f;
            int   bi = (hp < 5) ? ti[hp] : 0x7fffffff;
            float wv2 = bv; int wi2 = bi;
            for (int off = 16; off; off >>= 1) {
                float ov = __shfl_xor_sync(0xffffffffu, wv2, off);
                int   oi = __shfl_xor_sync(0xffffffffu, wi2, off);
                if (better(ov, oi, wv2, wi2)) { wv2 = ov; wi2 = oi; }
            }
            if (tx == 0) { s_tv[w][s5] = wv2; s_ti[w][s5] = wi2; }
            if (hp < 5 && wi2 == bi && wv2 == bv) hp++;
        }
        if (tx == 0) s_lse[w] = m + logf(s);
    }
    __syncthreads();

    if (tid == 0) {
        float bp[KK];
        for (int k = 0; k < KK; k++) bp[k] = g_bp[k*BB + b];
        float cv[KK*KK]; int ct[KK*KK];
        for (int ko = 0; ko < KK; ko++)
            for (int q = 0; q < 5; q++) {
                cv[ko*5 + q] = bp[ko] + (s_tv[ko][q] - s_lse[ko]);  // bp + tp, jax order
                ct[ko*5 + q] = s_ti[ko][q];
            }
        bool used[KK*KK] = {};
        for (int kn = 0; kn < KK; kn++) {
            int bf = -1; float bv = 0.f;
            for (int f = 0; f < KK*KK; f++)
                if (!used[f] && (bf < 0 || cv[f] > bv)) { bv = cv[f]; bf = f; } // tie: lowest flat idx
            used[bf] = true;
            int org = bf / KK, tok = ct[bf];
            g_bp[kn*BB + b]      = bv;
            g_sel_org[kn*BB + b] = org;
            g_sel_tok[kn*BB + b] = tok;
            g_org_all[t*BB*KK + b*KK + kn] = org;
            g_tok_all[t*BB*KK + b*KK + kn] = tok;
        }
    }
}

// ---------------- backtrack the beam pointer chains ----------------
__global__ void k_backtrack() {
    int i = threadIdx.x;
    if (i >= BB*KK) return;
    int b = i / KK, k = i % KK;
    int idx = k;
    for (int t = TT - 1; t >= 0; t--) {
        int o   = g_org_all[t*BB*KK + b*KK + idx];
        int tok = g_tok_all[t*BB*KK + b*KK + idx];
        g_bt_slot[(b*KK + k)*TT + t] = o;
        g_bt_tok [(b*KK + k)*TT + t] = tok;
        idx = o;
    }
}

// ---------------- final output: logits + outputs(==y_hard) + y_hard ----------------
__global__ void k_write(float* __restrict__ out) {
    int q = blockIdx.x;
    int b = q / (KK*TT);
    int rem = q % (KK*TT);
    int k = rem / TT, t = rem % TT;
    int s   = g_bt_slot[(b*KK + k)*TT + t];
    int tok = g_bt_tok [(b*KK + k)*TT + t];
    const float4* src = (const float4*)&g_out_all[(((size_t)t*KK + s)*BB + b)*VV];
    size_t N   = (size_t)BB*KK*TT*VV;
    size_t off = (((size_t)b*KK + k)*TT + t)*(size_t)VV;
    float4* d0 = (float4*)(out + off);
    float4* d1 = (float4*)(out + N + off);
    float4* d2 = (float4*)(out + 2*N + off);
    for (int i = threadIdx.x; i < VV/4; i += blockDim.x) {
        d0[i] = src[i];
        int vb = i*4;
        float4 h;
        h.x = (vb     == tok) ? 1.f : 0.f;
        h.y = (vb + 1 == tok) ? 1.f : 0.f;
        h.z = (vb + 2 == tok) ? 1.f : 0.f;
        h.w = (vb + 3 == tok) ? 1.f : 0.f;
        d1[i] = h;
        d2[i] = h;
    }
}

// ---------------- launch ----------------
extern "C" void kernel_launch(void* const* d_in, const int* in_sizes, int n_in,
                              void* d_out, int out_size) {
    const float* attrs = (const float*)d_in[0];
    const int*   bos   = (const int*)  d_in[1];
    const float* emb   = (const float*)d_in[4];
    const float* w_ih  = (const float*)d_in[5];
    const float* b_ih  = (const float*)d_in[6];
    const float* w_hh  = (const float*)d_in[7];
    const float* b_hh  = (const float*)d_in[8];
    const float* tw    = (const float*)d_in[9];
    const float* tb    = (const float*)d_in[10];
    const float* lw    = (const float*)d_in[11];
    const float* lb    = (const float*)d_in[12];
    float* out = (float*)d_out;

    k_init<<<BB, 128>>>(attrs, tw, tb, bos);
    for (int t = 0; t < TT; t++) {
        int prev = t & 1, cur = prev ^ 1;
        k_gru_gemm<<<dim3(G3/JT, 1, 2), 256>>>(emb, w_ih, b_ih, w_hh, b_hh, prev);
        k_gru_gates<<<(GG*HH + 255)/256, 256>>>(prev, cur);
        k_linear<<<NBLK, 256>>>(lw, lb, t, cur);
        k_reduce_select<<<BB, 256>>>(t);
    }
    k_backtrack<<<1, 64>>>();
    k_write<<<BB*KK*TT, 256>>>(out);
}

// round 5
// speedup vs baseline: 1.0976x; 1.0976x over previous
#include <cuda_runtime.h>
#include <cuda_bf16.h>
#include <cstdint>

#define BB 8
#define KK 5
#define TT 40
#define VV 32000
#define EE 256
#define HH 512
#define AA 512
#define GG (KK*BB)      /* 40 beam rows, g = k*BB + b */
#define G3 (3*HH)
#define NEGF (-1e9f)
#define NT 5            /* n-tiles of 8 over 40 beams */

// ---------------- small helpers ----------------
__device__ __forceinline__ uint32_t tf32r(float v){
    uint32_t u; asm("cvt.rna.tf32.f32 %0, %1;" : "=r"(u) : "f"(v)); return u;
}
__device__ __forceinline__ uint32_t bf16x2(float lo, float hi){
    uint32_t r; asm("cvt.rn.satfinite.bf16x2.f32 %0, %1, %2;" : "=r"(r) : "f"(hi), "f"(lo)); return r;
}
__device__ __forceinline__ bool better(float av, int ai, float bv, int bi) {
    return (av > bv) || (av == bv && ai < bi);
}

#define MMA_TF32(c, a, b0, b1) \
    asm volatile("mma.sync.aligned.m16n8k8.row.col.f32.tf32.tf32.f32 " \
        "{%0,%1,%2,%3}, {%4,%5,%6,%7}, {%8,%9}, {%0,%1,%2,%3};" \
        : "+f"((c)[0]), "+f"((c)[1]), "+f"((c)[2]), "+f"((c)[3]) \
        : "r"((a).x), "r"((a).y), "r"((a).z), "r"((a).w), "r"(b0), "r"(b1))

#define MMA_BF16(c, a, b0, b1) \
    asm volatile("mma.sync.aligned.m16n8k16.row.col.f32.bf16.bf16.f32 " \
        "{%0,%1,%2,%3}, {%4,%5,%6,%7}, {%8,%9}, {%0,%1,%2,%3};" \
        : "+f"((c)[0]), "+f"((c)[1]), "+f"((c)[2]), "+f"((c)[3]) \
        : "r"((a).x), "r"((a).y), "r"((a).z), "r"((a).w), "r"(b0), "r"(b1))

// ---------------- persistent device state ----------------
__device__ float g_hn[2][GG*HH];
__device__ float g_gp[2*8*GG*G3];                  // GRU partial sums [mode][c][g][j]
__device__ float g_bp[GG];
__device__ int   g_sel_org[GG];
__device__ int   g_sel_tok[GG];
__device__ int   g_org_all[TT*BB*KK];
__device__ int   g_tok_all[TT*BB*KK];
__device__ __align__(16) float g_out_all[(size_t)TT*GG*VV];
// packed MMA fragments (weights prepped once; beams per step)
__device__ __align__(16) float    g_pa_hi[(size_t)VV*HH];      // tf32-rounded fp32
__device__ __align__(16) uint32_t g_pa_lo[(size_t)VV*HH/2];    // bf16 residual pairs
__device__ __align__(16) float    g_pb_hi[NT*16*2*32*4];
__device__ __align__(16) float    g_pb_lo[NT*16*2*32*4];
__device__ __align__(16) uint32_t g_pb_bf[NT*16*32*4];
__device__ float g_tv[GG][5];
__device__ int   g_ti[GG][5];
__device__ float g_mx[GG];
__device__ float g_ls[GG];
__device__ int   g_tick;
__device__ int   g_bt_slot[BB*KK*TT];
__device__ int   g_bt_tok [BB*KK*TT];

// ---------------- weight fragment prep (coalesced writes, once per launch) ----------------
__global__ void k_prep_hi(const float* __restrict__ lw) {
    int idx = blockIdx.x*256 + threadIdx.x;               // one uint4 of g_pa_hi
    if (idx >= VV*HH/4) return;
    int vtile = idx >> 11, rem = idx & 2047;
    int kc = rem >> 7, rem2 = rem & 127;
    int s = rem2 >> 5, lane = rem2 & 31;
    int vb = vtile*16 + (lane >> 2);
    int hb = kc*32 + s*8 + (lane & 3);
    uint4 r;
    r.x = tf32r(lw[(size_t)(vb    )*HH + hb    ]);
    r.y = tf32r(lw[(size_t)(vb + 8)*HH + hb    ]);
    r.z = tf32r(lw[(size_t)(vb    )*HH + hb + 4]);
    r.w = tf32r(lw[(size_t)(vb + 8)*HH + hb + 4]);
    reinterpret_cast<uint4*>(g_pa_hi)[idx] = r;
}
__global__ void k_prep_lo(const float* __restrict__ lw) {
    int idx = blockIdx.x*256 + threadIdx.x;               // one uint4 of g_pa_lo
    if (idx >= VV*HH/8) return;
    int vtile = idx >> 10, rem = idx & 1023;
    int kc = rem >> 6, rem2 = rem & 63;
    int s2 = rem2 >> 5, lane = rem2 & 31;
    int vb = vtile*16 + (lane >> 2);
    uint32_t u[4];
    #pragma unroll
    for (int rr = 0; rr < 4; rr++) {
        int v = vb + 8*(rr & 1);
        int h = kc*32 + s2*16 + (rr >> 1)*8 + (lane & 3)*2;
        float w0 = lw[(size_t)v*HH + h], w1 = lw[(size_t)v*HH + h + 1];
        float h0 = __uint_as_float(tf32r(w0)), h1 = __uint_as_float(tf32r(w1));
        u[rr] = bf16x2(w0 - h0, w1 - h1);
    }
    reinterpret_cast<uint4*>(g_pa_lo)[idx] = make_uint4(u[0], u[1], u[2], u[3]);
}

// ---------------- init ----------------
__global__ void k_init(const float* __restrict__ attrs, const float* __restrict__ tw,
                       const float* __restrict__ tb, const int* __restrict__ bosp) {
    __shared__ float sa[AA];
    int b = blockIdx.x;
    for (int i = threadIdx.x; i < AA; i += blockDim.x) sa[i] = attrs[b*AA + i];
    __syncthreads();
    for (int j = threadIdx.x; j < HH; j += blockDim.x) {
        const float* w = &tw[(size_t)j*AA];
        float acc = 0.f;
        for (int a = 0; a < AA; a++) acc += sa[a] * w[a];
        acc += tb[j];
        for (int k = 0; k < KK; k++) g_hn[0][(k*BB + b)*HH + j] = acc;
    }
    if (b == 0 && threadIdx.x < GG) {
        int i = threadIdx.x, k = i / BB;
        g_bp[i] = (k == 0) ? 0.f : NEGF;
        g_sel_org[i] = k;
        g_sel_tok[i] = bosp[0];
        if (i == 0) g_tick = 0;
    }
}

// ---------------- GRU gate GEMMs, K-split ----------------
__global__ __launch_bounds__(256)
void k_gru_gemm(const float* __restrict__ emb,
                const float* __restrict__ w_ih, const float* __restrict__ w_hh, int prev) {
    const int mode = blockIdx.z;                 // 0: gi (E=256, 4 chunks), 1: gh (8 chunks)
    const int c = blockIdx.y;
    if (c >= (mode ? 8 : 4)) return;
    const int KIN = mode ? HH : EE;
    const float* __restrict__ W = mode ? w_hh : w_ih;

    __shared__ float wt[64][129];
    __shared__ float it[GG * 64];
    int tid = threadIdx.x, tx = tid & 31, ty = tid >> 5;
    int j0 = blockIdx.x * 128, kk0 = c * 64;
    float acc[4][5] = {};

    for (int idx = tid; idx < 128*16; idx += 256) {
        int jl = idx >> 4, q = idx & 15;
        float4 w4 = *reinterpret_cast<const float4*>(&W[(size_t)(j0 + jl)*KIN + kk0 + q*4]);
        wt[q*4+0][jl] = w4.x; wt[q*4+1][jl] = w4.y; wt[q*4+2][jl] = w4.z; wt[q*4+3][jl] = w4.w;
    }
    for (int idx = tid; idx < GG*16; idx += 256) {
        int g = idx >> 4, q = idx & 15;
        const float* src;
        if (mode == 0) src = &emb[(size_t)g_sel_tok[g] * EE];
        else { int b = g % BB; src = &g_hn[prev][(g_sel_org[g]*BB + b)*HH]; }
        *reinterpret_cast<float4*>(&it[g*64 + q*4]) =
            *reinterpret_cast<const float4*>(&src[kk0 + q*4]);
    }
    __syncthreads();
    for (int kk = 0; kk < 64; kk++) {
        float wv[4];
        #pragma unroll
        for (int i = 0; i < 4; i++) wv[i] = wt[kk][i*32 + tx];
        #pragma unroll
        for (int r = 0; r < 5; r++) {
            float xv = it[(ty + 8*r)*64 + kk];
            #pragma unroll
            for (int i = 0; i < 4; i++) acc[i][r] += wv[i] * xv;
        }
    }
    float* outp = &g_gp[(size_t)(mode*8 + c)*GG*G3];
    #pragma unroll
    for (int r = 0; r < 5; r++) {
        int g = ty + 8*r;
        #pragma unroll
        for (int i = 0; i < 4; i++) outp[(size_t)g*G3 + j0 + i*32 + tx] = acc[i][r];
    }
}

// ---------------- GRU gates + beam B-fragment packing ----------------
__global__ void k_gru_gates(const float* __restrict__ b_ih, const float* __restrict__ b_hh,
                            int prev, int cur) {
    int idx = blockIdx.x * blockDim.x + threadIdx.x;
    if (idx >= GG*HH) return;
    int g = idx / HH, j = idx % HH, b = g % BB;
    float gi[3] = {b_ih[j], b_ih[HH+j], b_ih[2*HH+j]};
    float gh[3] = {b_hh[j], b_hh[HH+j], b_hh[2*HH+j]};
    #pragma unroll
    for (int c = 0; c < 4; c++) {
        const float* p = &g_gp[(size_t)c*GG*G3 + (size_t)g*G3];
        gi[0] += p[j]; gi[1] += p[HH+j]; gi[2] += p[2*HH+j];
    }
    #pragma unroll
    for (int c = 0; c < 8; c++) {
        const float* p = &g_gp[(size_t)(8 + c)*GG*G3 + (size_t)g*G3];
        gh[0] += p[j]; gh[1] += p[HH+j]; gh[2] += p[2*HH+j];
    }
    float hprev = g_hn[prev][(g_sel_org[g]*BB + b)*HH + j];
    float r = 1.f / (1.f + expf(-(gi[0] + gh[0])));
    float z = 1.f / (1.f + expf(-(gi[1] + gh[1])));
    float n = tanhf(gi[2] + r*gh[2]);
    float hv = (1.f - z)*n + z*hprev;
    g_hn[cur][g*HH + j] = hv;

    // scatter into B fragment arrays
    int nt = g >> 3, gr = g & 7;
    int kc = j >> 5, jj = j & 31;
    // tf32 hi/lo (m16n8k8 B, col)
    {
        int s = jj >> 3, pos = jj & 7, l4 = pos & 3, half = pos >> 2;
        int lane = gr*4 + l4;
        int fi = ((nt*16 + kc)*2 + (s >> 1))*128 + lane*4 + (s & 1)*2 + half;
        float hi = __uint_as_float(tf32r(hv));
        g_pb_hi[fi] = hi;
        g_pb_lo[fi] = hv - hi;
    }
    // bf16 (m16n8k16 B, col)
    {
        int s2 = jj >> 4, kk2 = jj & 15;
        int breg = kk2 >> 3, halfb = kk2 & 1, l4b = (kk2 & 7) >> 1;
        int laneb = gr*4 + l4b;
        int ui = ((nt*16 + kc)*32 + laneb)*4 + s2*2 + breg;
        reinterpret_cast<__nv_bfloat16*>(g_pb_bf)[ui*2 + halfb] = __float2bfloat16(hv);
    }
}

// ---------------- vocab projection via mma.sync (3-term split) ----------------
__global__ __launch_bounds__(256)
void k_linear_mma(const float* __restrict__ lb, int t) {
    __shared__ float smd[GG * 132];
    int tid = threadIdx.x, warp = tid >> 5, lane = tid & 31;
    int vtile = blockIdx.x*8 + warp;

    const uint4* pA  = reinterpret_cast<const uint4*>(g_pa_hi) + (size_t)vtile*2048 + lane;
    const uint4* pAl = reinterpret_cast<const uint4*>(g_pa_lo) + (size_t)vtile*1024 + lane;
    const uint4* pBh = reinterpret_cast<const uint4*>(g_pb_hi) + lane;
    const uint4* pBl = reinterpret_cast<const uint4*>(g_pb_lo) + lane;
    const uint4* pBb = reinterpret_cast<const uint4*>(g_pb_bf) + lane;

    float acc[NT][4] = {};
    #pragma unroll 2
    for (int kc = 0; kc < 16; kc++) {
        uint4 A[4], Al[2], Bh[NT][2], Bl[NT][2], Bb[NT];
        #pragma unroll
        for (int s = 0; s < 4; s++) A[s] = pA[(kc*4 + s)*32];
        #pragma unroll
        for (int s2 = 0; s2 < 2; s2++) Al[s2] = pAl[(kc*2 + s2)*32];
        #pragma unroll
        for (int nt = 0; nt < NT; nt++) {
            Bh[nt][0] = pBh[nt*1024 + (kc*2    )*32];
            Bh[nt][1] = pBh[nt*1024 + (kc*2 + 1)*32];
            Bl[nt][0] = pBl[nt*1024 + (kc*2    )*32];
            Bl[nt][1] = pBl[nt*1024 + (kc*2 + 1)*32];
            Bb[nt]    = pBb[nt*512 + kc*32];
        }
        #pragma unroll
        for (int s = 0; s < 4; s++) {
            int hi = s >> 1, sub = s & 1;
            #pragma unroll
            for (int nt = 0; nt < NT; nt++) {
                uint32_t b0 = sub ? Bh[nt][hi].z : Bh[nt][hi].x;
                uint32_t b1 = sub ? Bh[nt][hi].w : Bh[nt][hi].y;
                MMA_TF32(acc[nt], A[s], b0, b1);
                uint32_t c0 = sub ? Bl[nt][hi].z : Bl[nt][hi].x;
                uint32_t c1 = sub ? Bl[nt][hi].w : Bl[nt][hi].y;
                MMA_TF32(acc[nt], A[s], c0, c1);
            }
        }
        #pragma unroll
        for (int s2 = 0; s2 < 2; s2++) {
            #pragma unroll
            for (int nt = 0; nt < NT; nt++) {
                uint32_t b0 = s2 ? Bb[nt].z : Bb[nt].x;
                uint32_t b1 = s2 ? Bb[nt].w : Bb[nt].y;
                MMA_BF16(acc[nt], Al[s2], b0, b1);
            }
        }
    }

    // transpose through smem for coalesced stores
    #pragma unroll
    for (int nt = 0; nt < NT; nt++) {
        #pragma unroll
        for (int r = 0; r < 4; r++) {
            int g = nt*8 + (lane & 3)*2 + (r & 1);
            int vloc = warp*16 + (lane >> 2) + (r >> 1)*8;
            smd[g*132 + vloc] = acc[nt][r];
        }
    }
    __syncthreads();
    int v0 = blockIdx.x * 128;
    float4 b4 = *reinterpret_cast<const float4*>(&lb[v0 + (tid & 31)*4]);
    for (int g = tid >> 5; g < GG; g += 8) {
        float4 x = *reinterpret_cast<float4*>(&smd[g*132 + (tid & 31)*4]);
        x.x += b4.x; x.y += b4.y; x.z += b4.z; x.w += b4.w;
        *reinterpret_cast<float4*>(&g_out_all[((size_t)t*GG + g)*VV + v0 + (tid & 31)*4]) = x;
    }
}

// ---------------- per-row softmax stats + top5, fused beam combine ----------------
__global__ __launch_bounds__(256)
void k_select(int t) {
    int g = blockIdx.x;
    int tid = threadIdx.x, tx = tid & 31, w = tid >> 5;
    const float* row = &g_out_all[((size_t)t*GG + g)*VV];
    __shared__ float s_red[8];
    __shared__ float s_wv[8][5];
    __shared__ int   s_wi[8][5];
    __shared__ int   s_flag;

    float tv[5]; int ti[5];
    #pragma unroll
    for (int i = 0; i < 5; i++) { tv[i] = -1e38f; ti[i] = 0x7fffffff; }
    float m = -1e38f;
    for (int v = tid; v < VV; v += 256) {
        float x = row[v];
        m = fmaxf(m, x);
        if (better(x, v, tv[4], ti[4])) {
            tv[4] = x; ti[4] = v;
            #pragma unroll
            for (int j = 4; j > 0; j--)
                if (better(tv[j], ti[j], tv[j-1], ti[j-1])) {
                    float fv = tv[j]; tv[j] = tv[j-1]; tv[j-1] = fv;
                    int   fi = ti[j]; ti[j] = ti[j-1]; ti[j-1] = fi;
                }
        }
    }
    for (int o = 16; o; o >>= 1) m = fmaxf(m, __shfl_xor_sync(~0u, m, o));
    if (tx == 0) s_red[w] = m;
    __syncthreads();
    float M = s_red[0];
    #pragma unroll
    for (int i = 1; i < 8; i++) M = fmaxf(M, s_red[i]);

    int hp = 0;
    for (int s5 = 0; s5 < 5; s5++) {
        float bv = (hp < 5) ? tv[hp] : -1e38f;
        int   bi = (hp < 5) ? ti[hp] : 0x7fffffff;
        float wv2 = bv; int wi2 = bi;
        for (int o = 16; o; o >>= 1) {
            float ov = __shfl_xor_sync(~0u, wv2, o);
            int   oi = __shfl_xor_sync(~0u, wi2, o);
            if (better(ov, oi, wv2, wi2)) { wv2 = ov; wi2 = oi; }
        }
        if (tx == 0) { s_wv[w][s5] = wv2; s_wi[w][s5] = wi2; }
        if (hp < 5 && wi2 == bi && wv2 == bv) hp++;
    }

    float s = 0.f;
    for (int v = tid; v < VV; v += 256) s += expf(row[v] - M);
    for (int o = 16; o; o >>= 1) s += __shfl_xor_sync(~0u, s, o);
    __syncthreads();
    if (tx == 0) s_red[w] = s;
    __syncthreads();

    if (tid == 0) {
        float S = 0.f;
        #pragma unroll
        for (int i = 0; i < 8; i++) S += s_red[i];
        float fv[5]; int fi[5];
        int hpw[8] = {};
        for (int s5 = 0; s5 < 5; s5++) {
            int bw = -1; float bv = 0.f; int bi = 0;
            for (int ww = 0; ww < 8; ww++) {
                if (hpw[ww] >= 5) continue;
                float cv = s_wv[ww][hpw[ww]]; int ci = s_wi[ww][hpw[ww]];
                if (bw < 0 || better(cv, ci, bv, bi)) { bv = cv; bi = ci; bw = ww; }
            }
            fv[s5] = bv; fi[s5] = bi; hpw[bw]++;
        }
        #pragma unroll
        for (int i = 0; i < 5; i++) { g_tv[g][i] = fv[i]; g_ti[g][i] = fi[i]; }
        g_mx[g] = M;
        g_ls[g] = logf(S);
        __threadfence();
        int r = atomicAdd(&g_tick, 1);
        s_flag = (r == GG - 1) ? 1 : 0;
    }
    __syncthreads();

    if (s_flag) {
        __threadfence();
        if (tid < BB) {
            int b = tid;
            float bp[KK]; float cv[KK*KK]; int ct[KK*KK];
            for (int k = 0; k < KK; k++) bp[k] = g_bp[k*BB + b];
            for (int ko = 0; ko < KK; ko++) {
                int gg = ko*BB + b;
                float Mg = g_mx[gg], Lg = g_ls[gg];
                for (int q = 0; q < KK; q++) {
                    float tp = (g_tv[gg][q] - Mg) - Lg;   // matches jax log_softmax rounding
                    cv[ko*KK + q] = bp[ko] + tp;
                    ct[ko*KK + q] = g_ti[gg][q];
                }
            }
            bool used[KK*KK] = {};
            for (int kn = 0; kn < KK; kn++) {
                int bf = -1; float bv = 0.f;
                for (int f = 0; f < KK*KK; f++)
                    if (!used[f] && (bf < 0 || cv[f] > bv)) { bv = cv[f]; bf = f; }
                used[bf] = true;
                int org = bf / KK, tok = ct[bf];
                g_bp[kn*BB + b] = bv;
                g_sel_org[kn*BB + b] = org;
                g_sel_tok[kn*BB + b] = tok;
                g_org_all[t*BB*KK + b*KK + kn] = org;
                g_tok_all[t*BB*KK + b*KK + kn] = tok;
            }
        }
        if (tid == 0) g_tick = 0;
    }
}

// ---------------- backtrack + final write ----------------
__global__ void k_backtrack() {
    int i = threadIdx.x;
    if (i >= BB*KK) return;
    int b = i / KK, k = i % KK, idx = k;
    for (int t = TT - 1; t >= 0; t--) {
        int o = g_org_all[t*BB*KK + b*KK + idx];
        g_bt_slot[(b*KK + k)*TT + t] = o;
        g_bt_tok [(b*KK + k)*TT + t] = g_tok_all[t*BB*KK + b*KK + idx];
        idx = o;
    }
}

__global__ void k_write(float* __restrict__ out) {
    int q = blockIdx.x;
    int b = q / (KK*TT), rem = q % (KK*TT);
    int k = rem / TT, t = rem % TT;
    int s = g_bt_slot[(b*KK + k)*TT + t];
    int tok = g_bt_tok[(b*KK + k)*TT + t];
    const float4* src = (const float4*)&g_out_all[((size_t)t*GG + (s*BB + b))*VV];
    size_t N = (size_t)BB*KK*TT*VV;
    size_t off = (((size_t)b*KK + k)*TT + t)*(size_t)VV;
    float4* d0 = (float4*)(out + off);
    float4* d1 = (float4*)(out + N + off);
    float4* d2 = (float4*)(out + 2*N + off);
    for (int i = threadIdx.x; i < VV/4; i += blockDim.x) {
        d0[i] = src[i];
        int vb = i*4;
        float4 h;
        h.x = (vb == tok) ? 1.f : 0.f;  h.y = (vb+1 == tok) ? 1.f : 0.f;
        h.z = (vb+2 == tok) ? 1.f : 0.f; h.w = (vb+3 == tok) ? 1.f : 0.f;
        d1[i] = h; d2[i] = h;
    }
}

// ---------------- launch ----------------
extern "C" void kernel_launch(void* const* d_in, const int* in_sizes, int n_in,
                              void* d_out, int out_size) {
    const float* attrs = (const float*)d_in[0];
    const int*   bos   = (const int*)  d_in[1];
    const float* emb   = (const float*)d_in[4];
    const float* w_ih  = (const float*)d_in[5];
    const float* b_ih  = (const float*)d_in[6];
    const float* w_hh  = (const float*)d_in[7];
    const float* b_hh  = (const float*)d_in[8];
    const float* tw    = (const float*)d_in[9];
    const float* tb    = (const float*)d_in[10];
    const float* lw    = (const float*)d_in[11];
    const float* lb    = (const float*)d_in[12];
    float* out = (float*)d_out;

    k_prep_hi<<<(VV*HH/4 + 255)/256, 256>>>(lw);
    k_prep_lo<<<(VV*HH/8 + 255)/256, 256>>>(lw);
    k_init<<<BB, 128>>>(attrs, tw, tb, bos);
    for (int t = 0; t < TT; t++) {
        int prev = t & 1, cur = prev ^ 1;
        k_gru_gemm<<<dim3(G3/128, 8, 2), 256>>>(emb, w_ih, w_hh, prev);
        k_gru_gates<<<(GG*HH + 255)/256, 256>>>(b_ih, b_hh, prev, cur);
        k_linear_mma<<<VV/128, 256>>>(lb, t);
        k_select<<<GG, 256>>>(t);
    }
    k_backtrack<<<1, 64>>>();
    k_write<<<BB*KK*TT, 256>>>(out);
}

// round 6
// speedup vs baseline: 1.1035x; 1.0054x over previous
#include <cuda_runtime.h>
#include <cuda_bf16.h>
#include <cstdint>

#define BB 8
#define KK 5
#define TT 40
#define VV 32000
#define EE 256
#define HH 512
#define AA 512
#define GG (KK*BB)      /* 40 beam rows, g = k*BB + b */
#define G3 (3*HH)
#define NEGF (-1e9f)
#define NT 5            /* n-tiles of 8 over 40 beams */

// ---------------- small helpers ----------------
__device__ __forceinline__ uint32_t tf32r(float v){
    uint32_t u; asm("cvt.rna.tf32.f32 %0, %1;" : "=r"(u) : "f"(v)); return u;
}
__device__ __forceinline__ uint32_t bf16x2(float lo, float hi){
    uint32_t r; asm("cvt.rn.satfinite.bf16x2.f32 %0, %1, %2;" : "=r"(r) : "f"(hi), "f"(lo)); return r;
}
__device__ __forceinline__ bool better(float av, int ai, float bv, int bi) {
    return (av > bv) || (av == bv && ai < bi);
}

#define MMA_TF32(c, a, b0, b1) \
    asm volatile("mma.sync.aligned.m16n8k8.row.col.f32.tf32.tf32.f32 " \
        "{%0,%1,%2,%3}, {%4,%5,%6,%7}, {%8,%9}, {%0,%1,%2,%3};" \
        : "+f"((c)[0]), "+f"((c)[1]), "+f"((c)[2]), "+f"((c)[3]) \
        : "r"((a).x), "r"((a).y), "r"((a).z), "r"((a).w), "r"(b0), "r"(b1))

#define MMA_BF16(c, a, b0, b1) \
    asm volatile("mma.sync.aligned.m16n8k16.row.col.f32.bf16.bf16.f32 " \
        "{%0,%1,%2,%3}, {%4,%5,%6,%7}, {%8,%9}, {%0,%1,%2,%3};" \
        : "+f"((c)[0]), "+f"((c)[1]), "+f"((c)[2]), "+f"((c)[3]) \
        : "r"((a).x), "r"((a).y), "r"((a).z), "r"((a).w), "r"(b0), "r"(b1))

// ---------------- persistent device state ----------------
__device__ float g_hn[2][GG*HH];
__device__ float g_gp[2*8*GG*G3];                  // GRU partial sums [mode][c][g][j]
__device__ float g_bp[GG];
__device__ int   g_sel_org[GG];
__device__ int   g_sel_tok[GG];
__device__ int   g_org_all[TT*BB*KK];
__device__ int   g_tok_all[TT*BB*KK];
__device__ __align__(16) float g_out_all[(size_t)TT*GG*VV];
// packed MMA fragments (weights prepped once; beams per step)
__device__ __align__(16) float    g_pa_hi[(size_t)VV*HH];      // tf32-rounded fp32
__device__ __align__(16) uint32_t g_pa_lo[(size_t)VV*HH/2];    // bf16 residual pairs
__device__ __align__(16) float    g_pb_hi[NT*16*2*32*4];
__device__ __align__(16) float    g_pb_lo[NT*16*2*32*4];
__device__ __align__(16) uint32_t g_pb_bf[NT*16*32*4];
__device__ float g_tv[GG][5];
__device__ int   g_ti[GG][5];
__device__ float g_mx[GG];
__device__ float g_ls[GG];
__device__ int   g_tick;
__device__ int   g_bt_slot[BB*KK*TT];
__device__ int   g_bt_tok [BB*KK*TT];

// ---------------- weight fragment prep (coalesced writes, once per launch) ----------------
__global__ void k_prep_hi(const float* __restrict__ lw) {
    int idx = blockIdx.x*256 + threadIdx.x;               // one uint4 of g_pa_hi
    if (idx >= VV*HH/4) return;
    int vtile = idx >> 11, rem = idx & 2047;
    int kc = rem >> 7, rem2 = rem & 127;
    int s = rem2 >> 5, lane = rem2 & 31;
    int vb = vtile*16 + (lane >> 2);
    int hb = kc*32 + s*8 + (lane & 3);
    uint4 r;
    r.x = tf32r(lw[(size_t)(vb    )*HH + hb    ]);
    r.y = tf32r(lw[(size_t)(vb + 8)*HH + hb    ]);
    r.z = tf32r(lw[(size_t)(vb    )*HH + hb + 4]);
    r.w = tf32r(lw[(size_t)(vb + 8)*HH + hb + 4]);
    reinterpret_cast<uint4*>(g_pa_hi)[idx] = r;
}
__global__ void k_prep_lo(const float* __restrict__ lw) {
    int idx = blockIdx.x*256 + threadIdx.x;               // one uint4 of g_pa_lo
    if (idx >= VV*HH/8) return;
    int vtile = idx >> 10, rem = idx & 1023;
    int kc = rem >> 6, rem2 = rem & 63;
    int s2 = rem2 >> 5, lane = rem2 & 31;
    int vb = vtile*16 + (lane >> 2);
    uint32_t u[4];
    #pragma unroll
    for (int rr = 0; rr < 4; rr++) {
        int v = vb + 8*(rr & 1);
        int h = kc*32 + s2*16 + (rr >> 1)*8 + (lane & 3)*2;
        float w0 = lw[(size_t)v*HH + h], w1 = lw[(size_t)v*HH + h + 1];
        float h0 = __uint_as_float(tf32r(w0)), h1 = __uint_as_float(tf32r(w1));
        u[rr] = bf16x2(w0 - h0, w1 - h1);
    }
    reinterpret_cast<uint4*>(g_pa_lo)[idx] = make_uint4(u[0], u[1], u[2], u[3]);
}

// ---------------- init ----------------
__global__ void k_init(const float* __restrict__ attrs, const float* __restrict__ tw,
                       const float* __restrict__ tb, const int* __restrict__ bosp) {
    __shared__ float sa[AA];
    int b = blockIdx.x;
    for (int i = threadIdx.x; i < AA; i += blockDim.x) sa[i] = attrs[b*AA + i];
    __syncthreads();
    for (int j = threadIdx.x; j < HH; j += blockDim.x) {
        const float* w = &tw[(size_t)j*AA];
        float acc = 0.f;
        for (int a = 0; a < AA; a++) acc += sa[a] * w[a];
        acc += tb[j];
        for (int k = 0; k < KK; k++) g_hn[0][(k*BB + b)*HH + j] = acc;
    }
    if (b == 0 && threadIdx.x < GG) {
        int i = threadIdx.x, k = i / BB;
        g_bp[i] = (k == 0) ? 0.f : NEGF;
        g_sel_org[i] = k;
        g_sel_tok[i] = bosp[0];
        if (i == 0) g_tick = 0;
    }
}

// ---------------- GRU gate GEMMs, K-split ----------------
__global__ __launch_bounds__(256)
void k_gru_gemm(const float* __restrict__ emb,
                const float* __restrict__ w_ih, const float* __restrict__ w_hh, int prev) {
    const int mode = blockIdx.z;                 // 0: gi (E=256, 4 chunks), 1: gh (8 chunks)
    const int c = blockIdx.y;
    if (c >= (mode ? 8 : 4)) return;
    const int KIN = mode ? HH : EE;
    const float* __restrict__ W = mode ? w_hh : w_ih;

    __shared__ float wt[64][129];
    __shared__ float it[GG * 64];
    int tid = threadIdx.x, tx = tid & 31, ty = tid >> 5;
    int j0 = blockIdx.x * 128, kk0 = c * 64;
    float acc[4][5] = {};

    for (int idx = tid; idx < 128*16; idx += 256) {
        int jl = idx >> 4, q = idx & 15;
        float4 w4 = *reinterpret_cast<const float4*>(&W[(size_t)(j0 + jl)*KIN + kk0 + q*4]);
        wt[q*4+0][jl] = w4.x; wt[q*4+1][jl] = w4.y; wt[q*4+2][jl] = w4.z; wt[q*4+3][jl] = w4.w;
    }
    for (int idx = tid; idx < GG*16; idx += 256) {
        int g = idx >> 4, q = idx & 15;
        const float* src;
        if (mode == 0) src = &emb[(size_t)g_sel_tok[g] * EE];
        else { int b = g % BB; src = &g_hn[prev][(g_sel_org[g]*BB + b)*HH]; }
        *reinterpret_cast<float4*>(&it[g*64 + q*4]) =
            *reinterpret_cast<const float4*>(&src[kk0 + q*4]);
    }
    __syncthreads();
    for (int kk = 0; kk < 64; kk++) {
        float wv[4];
        #pragma unroll
        for (int i = 0; i < 4; i++) wv[i] = wt[kk][i*32 + tx];
        #pragma unroll
        for (int r = 0; r < 5; r++) {
            float xv = it[(ty + 8*r)*64 + kk];
            #pragma unroll
            for (int i = 0; i < 4; i++) acc[i][r] += wv[i] * xv;
        }
    }
    float* outp = &g_gp[(size_t)(mode*8 + c)*GG*G3];
    #pragma unroll
    for (int r = 0; r < 5; r++) {
        int g = ty + 8*r;
        #pragma unroll
        for (int i = 0; i < 4; i++) outp[(size_t)g*G3 + j0 + i*32 + tx] = acc[i][r];
    }
}

// ---------------- GRU gates + beam B-fragment packing ----------------
__global__ void k_gru_gates(const float* __restrict__ b_ih, const float* __restrict__ b_hh,
                            int prev, int cur) {
    int idx = blockIdx.x * blockDim.x + threadIdx.x;
    if (idx >= GG*HH) return;
    int g = idx / HH, j = idx % HH, b = g % BB;
    float gi[3] = {b_ih[j], b_ih[HH+j], b_ih[2*HH+j]};
    float gh[3] = {b_hh[j], b_hh[HH+j], b_hh[2*HH+j]};
    #pragma unroll
    for (int c = 0; c < 4; c++) {
        const float* p = &g_gp[(size_t)c*GG*G3 + (size_t)g*G3];
        gi[0] += p[j]; gi[1] += p[HH+j]; gi[2] += p[2*HH+j];
    }
    #pragma unroll
    for (int c = 0; c < 8; c++) {
        const float* p = &g_gp[(size_t)(8 + c)*GG*G3 + (size_t)g*G3];
        gh[0] += p[j]; gh[1] += p[HH+j]; gh[2] += p[2*HH+j];
    }
    float hprev = g_hn[prev][(g_sel_org[g]*BB + b)*HH + j];
    float r = 1.f / (1.f + expf(-(gi[0] + gh[0])));
    float z = 1.f / (1.f + expf(-(gi[1] + gh[1])));
    float n = tanhf(gi[2] + r*gh[2]);
    float hv = (1.f - z)*n + z*hprev;
    g_hn[cur][g*HH + j] = hv;

    // scatter into B fragment arrays
    int nt = g >> 3, gr = g & 7;
    int kc = j >> 5, jj = j & 31;
    // tf32 hi/lo (m16n8k8 B, col)
    {
        int s = jj >> 3, pos = jj & 7, l4 = pos & 3, half = pos >> 2;
        int lane = gr*4 + l4;
        int fi = ((nt*16 + kc)*2 + (s >> 1))*128 + lane*4 + (s & 1)*2 + half;
        float hi = __uint_as_float(tf32r(hv));
        g_pb_hi[fi] = hi;
        g_pb_lo[fi] = hv - hi;
    }
    // bf16 (m16n8k16 B, col)
    {
        int s2 = jj >> 4, kk2 = jj & 15;
        int breg = kk2 >> 3, halfb = kk2 & 1, l4b = (kk2 & 7) >> 1;
        int laneb = gr*4 + l4b;
        int ui = ((nt*16 + kc)*32 + laneb)*4 + s2*2 + breg;
        reinterpret_cast<__nv_bfloat16*>(g_pb_bf)[ui*2 + halfb] = __float2bfloat16(hv);
    }
}

// ---------------- vocab projection via mma.sync (3-term split) ----------------
__global__ __launch_bounds__(256)
void k_linear_mma(const float* __restrict__ lb, int t) {
    __shared__ float smd[GG * 132];
    int tid = threadIdx.x, warp = tid >> 5, lane = tid & 31;
    int vtile = blockIdx.x*8 + warp;

    const uint4* pA  = reinterpret_cast<const uint4*>(g_pa_hi) + (size_t)vtile*2048 + lane;
    const uint4* pAl = reinterpret_cast<const uint4*>(g_pa_lo) + (size_t)vtile*1024 + lane;
    const uint4* pBh = reinterpret_cast<const uint4*>(g_pb_hi) + lane;
    const uint4* pBl = reinterpret_cast<const uint4*>(g_pb_lo) + lane;
    const uint4* pBb = reinterpret_cast<const uint4*>(g_pb_bf) + lane;

    float acc[NT][4] = {};
    #pragma unroll 2
    for (int kc = 0; kc < 16; kc++) {
        uint4 A[4], Al[2], Bh[NT][2], Bl[NT][2], Bb[NT];
        #pragma unroll
        for (int s = 0; s < 4; s++) A[s] = pA[(kc*4 + s)*32];
        #pragma unroll
        for (int s2 = 0; s2 < 2; s2++) Al[s2] = pAl[(kc*2 + s2)*32];
        #pragma unroll
        for (int nt = 0; nt < NT; nt++) {
            Bh[nt][0] = pBh[nt*1024 + (kc*2    )*32];
            Bh[nt][1] = pBh[nt*1024 + (kc*2 + 1)*32];
            Bl[nt][0] = pBl[nt*1024 + (kc*2    )*32];
            Bl[nt][1] = pBl[nt*1024 + (kc*2 + 1)*32];
            Bb[nt]    = pBb[nt*512 + kc*32];
        }
        #pragma unroll
        for (int s = 0; s < 4; s++) {
            int hi = s >> 1, sub = s & 1;
            #pragma unroll
            for (int nt = 0; nt < NT; nt++) {
                uint32_t b0 = sub ? Bh[nt][hi].z : Bh[nt][hi].x;
                uint32_t b1 = sub ? Bh[nt][hi].w : Bh[nt][hi].y;
                MMA_TF32(acc[nt], A[s], b0, b1);
                uint32_t c0 = sub ? Bl[nt][hi].z : Bl[nt][hi].x;
                uint32_t c1 = sub ? Bl[nt][hi].w : Bl[nt][hi].y;
                MMA_TF32(acc[nt], A[s], c0, c1);
            }
        }
        #pragma unroll
        for (int s2 = 0; s2 < 2; s2++) {
            #pragma unroll
            for (int nt = 0; nt < NT; nt++) {
                uint32_t b0 = s2 ? Bb[nt].z : Bb[nt].x;
                uint32_t b1 = s2 ? Bb[nt].w : Bb[nt].y;
                MMA_BF16(acc[nt], Al[s2], b0, b1);
            }
        }
    }

    // transpose through smem for coalesced stores
    #pragma unroll
    for (int nt = 0; nt < NT; nt++) {
        #pragma unroll
        for (int r = 0; r < 4; r++) {
            int g = nt*8 + (lane & 3)*2 + (r & 1);
            int vloc = warp*16 + (lane >> 2) + (r >> 1)*8;
            smd[g*132 + vloc] = acc[nt][r];
        }
    }
    __syncthreads();
    int v0 = blockIdx.x * 128;
    float4 b4 = *reinterpret_cast<const float4*>(&lb[v0 + (tid & 31)*4]);
    for (int g = tid >> 5; g < GG; g += 8) {
        float4 x = *reinterpret_cast<float4*>(&smd[g*132 + (tid & 31)*4]);
        x.x += b4.x; x.y += b4.y; x.z += b4.z; x.w += b4.w;
        *reinterpret_cast<float4*>(&g_out_all[((size_t)t*GG + g)*VV + v0 + (tid & 31)*4]) = x;
    }
}

// ---------------- per-row softmax stats + top5, fused beam combine ----------------
__global__ __launch_bounds__(256)
void k_select(int t) {
    int g = blockIdx.x;
    int tid = threadIdx.x, tx = tid & 31, w = tid >> 5;
    const float* row = &g_out_all[((size_t)t*GG + g)*VV];
    __shared__ float s_red[8];
    __shared__ float s_wv[8][5];
    __shared__ int   s_wi[8][5];
    __shared__ int   s_flag;

    float tv[5]; int ti[5];
    #pragma unroll
    for (int i = 0; i < 5; i++) { tv[i] = -1e38f; ti[i] = 0x7fffffff; }
    float m = -1e38f;
    for (int v = tid; v < VV; v += 256) {
        float x = row[v];
        m = fmaxf(m, x);
        if (better(x, v, tv[4], ti[4])) {
            tv[4] = x; ti[4] = v;
            #pragma unroll
            for (int j = 4; j > 0; j--)
                if (better(tv[j], ti[j], tv[j-1], ti[j-1])) {
                    float fv = tv[j]; tv[j] = tv[j-1]; tv[j-1] = fv;
                    int   fi = ti[j]; ti[j] = ti[j-1]; ti[j-1] = fi;
                }
        }
    }
    for (int o = 16; o; o >>= 1) m = fmaxf(m, __shfl_xor_sync(~0u, m, o));
    if (tx == 0) s_red[w] = m;
    __syncthreads();
    float M = s_red[0];
    #pragma unroll
    for (int i = 1; i < 8; i++) M = fmaxf(M, s_red[i]);

    int hp = 0;
    for (int s5 = 0; s5 < 5; s5++) {
        float bv = (hp < 5) ? tv[hp] : -1e38f;
        int   bi = (hp < 5) ? ti[hp] : 0x7fffffff;
        float wv2 = bv; int wi2 = bi;
        for (int o = 16; o; o >>= 1) {
            float ov = __shfl_xor_sync(~0u, wv2, o);
            int   oi = __shfl_xor_sync(~0u, wi2, o);
            if (better(ov, oi, wv2, wi2)) { wv2 = ov; wi2 = oi; }
        }
        if (tx == 0) { s_wv[w][s5] = wv2; s_wi[w][s5] = wi2; }
        if (hp < 5 && wi2 == bi && wv2 == bv) hp++;
    }

    float s = 0.f;
    for (int v = tid; v < VV; v += 256) s += expf(row[v] - M);
    for (int o = 16; o; o >>= 1) s += __shfl_xor_sync(~0u, s, o);
    __syncthreads();
    if (tx == 0) s_red[w] = s;
    __syncthreads();

    if (tid == 0) {
        float S = 0.f;
        #pragma unroll
        for (int i = 0; i < 8; i++) S += s_red[i];
        float fv[5]; int fi[5];
        int hpw[8] = {};
        for (int s5 = 0; s5 < 5; s5++) {
            int bw = -1; float bv = 0.f; int bi = 0;
            for (int ww = 0; ww < 8; ww++) {
                if (hpw[ww] >= 5) continue;
                float cv = s_wv[ww][hpw[ww]]; int ci = s_wi[ww][hpw[ww]];
                if (bw < 0 || better(cv, ci, bv, bi)) { bv = cv; bi = ci; bw = ww; }
            }
            fv[s5] = bv; fi[s5] = bi; hpw[bw]++;
        }
        #pragma unroll
        for (int i = 0; i < 5; i++) { g_tv[g][i] = fv[i]; g_ti[g][i] = fi[i]; }
        g_mx[g] = M;
        g_ls[g] = logf(S);
        __threadfence();
        int r = atomicAdd(&g_tick, 1);
        s_flag = (r == GG - 1) ? 1 : 0;
    }
    __syncthreads();

    if (s_flag) {
        __threadfence();
        if (tid < BB) {
            int b = tid;
            float bp[KK]; float cv[KK*KK]; int ct[KK*KK];
            for (int k = 0; k < KK; k++) bp[k] = g_bp[k*BB + b];
            for (int ko = 0; ko < KK; ko++) {
                int gg = ko*BB + b;
                float Mg = g_mx[gg], Lg = g_ls[gg];
                for (int q = 0; q < KK; q++) {
                    float tp = (g_tv[gg][q] - Mg) - Lg;   // matches jax log_softmax rounding
                    cv[ko*KK + q] = bp[ko] + tp;
                    ct[ko*KK + q] = g_ti[gg][q];
                }
            }
            bool used[KK*KK] = {};
            for (int kn = 0; kn < KK; kn++) {
                int bf = -1; float bv = 0.f;
                for (int f = 0; f < KK*KK; f++)
                    if (!used[f] && (bf < 0 || cv[f] > bv)) { bv = cv[f]; bf = f; }
                used[bf] = true;
                int org = bf / KK, tok = ct[bf];
                g_bp[kn*BB + b] = bv;
                g_sel_org[kn*BB + b] = org;
                g_sel_tok[kn*BB + b] = tok;
                g_org_all[t*BB*KK + b*KK + kn] = org;
                g_tok_all[t*BB*KK + b*KK + kn] = tok;
            }
        }
        if (tid == 0) g_tick = 0;
    }
}

// ---------------- backtrack + final write ----------------
__global__ void k_backtrack() {
    int i = threadIdx.x;
    if (i >= BB*KK) return;
    int b = i / KK, k = i % KK, idx = k;
    for (int t = TT - 1; t >= 0; t--) {
        int o = g_org_all[t*BB*KK + b*KK + idx];
        g_bt_slot[(b*KK + k)*TT + t] = o;
        g_bt_tok [(b*KK + k)*TT + t] = g_tok_all[t*BB*KK + b*KK + idx];
        idx = o;
    }
}

__global__ void k_write(float* __restrict__ out) {
    int q = blockIdx.x;
    int b = q / (KK*TT), rem = q % (KK*TT);
    int k = rem / TT, t = rem % TT;
    int s = g_bt_slot[(b*KK + k)*TT + t];
    int tok = g_bt_tok[(b*KK + k)*TT + t];
    const float4* src = (const float4*)&g_out_all[((size_t)t*GG + (s*BB + b))*VV];
    size_t N = (size_t)BB*KK*TT*VV;
    size_t off = (((size_t)b*KK + k)*TT + t)*(size_t)VV;
    float4* d0 = (float4*)(out + off);
    float4* d1 = (float4*)(out + N + off);
    float4* d2 = (float4*)(out + 2*N + off);
    for (int i = threadIdx.x; i < VV/4; i += blockDim.x) {
        d0[i] = src[i];
        int vb = i*4;
        float4 h;
        h.x = (vb == tok) ? 1.f : 0.f;  h.y = (vb+1 == tok) ? 1.f : 0.f;
        h.z = (vb+2 == tok) ? 1.f : 0.f; h.w = (vb+3 == tok) ? 1.f : 0.f;
        d1[i] = h; d2[i] = h;
    }
}

// ---------------- launch ----------------
extern "C" void kernel_launch(void* const* d_in, const int* in_sizes, int n_in,
                              void* d_out, int out_size) {
    const float* attrs = (const float*)d_in[0];
    const int*   bos   = (const int*)  d_in[1];
    const float* emb   = (const float*)d_in[4];
    const float* w_ih  = (const float*)d_in[5];
    const float* b_ih  = (const float*)d_in[6];
    const float* w_hh  = (const float*)d_in[7];
    const float* b_hh  = (const float*)d_in[8];
    const float* tw    = (const float*)d_in[9];
    const float* tb    = (const float*)d_in[10];
    const float* lw    = (const float*)d_in[11];
    const float* lb    = (const float*)d_in[12];
    float* out = (float*)d_out;

    k_prep_hi<<<(VV*HH/4 + 255)/256, 256>>>(lw);
    k_prep_lo<<<(VV*HH/8 + 255)/256, 256>>>(lw);
    k_init<<<BB, 128>>>(attrs, tw, tb, bos);
    for (int t = 0; t < TT; t++) {
        int prev = t & 1, cur = prev ^ 1;
        k_gru_gemm<<<dim3(G3/128, 8, 2), 256>>>(emb, w_ih, w_hh, prev);
        k_gru_gates<<<(GG*HH + 255)/256, 256>>>(b_ih, b_hh, prev, cur);
        k_linear_mma<<<VV/128, 256>>>(lb, t);
        k_select<<<GG, 256>>>(t);
    }
    k_backtrack<<<1, 64>>>();
    k_write<<<BB*KK*TT, 256>>>(out);
}

// round 7
// speedup vs baseline: 1.9515x; 1.7684x over previous
#include <cuda_runtime.h>
#include <cuda_fp16.h>
#include <cstdint>

#define BB 8
#define KK 5
#define TT 40
#define VV 32000
#define EE 256
#define HH 512
#define AA 512
#define GG 40
#define G3 1536
#define NEGF (-1e9f)
#define NB 125
#define NTH 512
#define NT 5
#define NVT 2000

__device__ __forceinline__ bool better(float av, int ai, float bv, int bi) {
    return (av > bv) || (av == bv && ai < bi);
}
__device__ __forceinline__ void ins5(float* tv, int* ti, float v, int i) {
    if (better(v, i, tv[4], ti[4])) {
        tv[4] = v; ti[4] = i;
        #pragma unroll
        for (int j = 4; j > 0; j--)
            if (better(tv[j], ti[j], tv[j-1], ti[j-1])) {
                float fv = tv[j]; tv[j] = tv[j-1]; tv[j-1] = fv;
                int fi = ti[j]; ti[j] = ti[j-1]; ti[j-1] = fi;
            }
    }
}
__device__ __forceinline__ void warp_top5(float* tv, int* ti, float* rv, int* ri) {
    int hp = 0;
    #pragma unroll
    for (int s5 = 0; s5 < 5; s5++) {
        float bv = (hp < 5) ? tv[hp] : -1e38f;
        int   bi = (hp < 5) ? ti[hp] : 0x7fffffff;
        float wv = bv; int wi = bi;
        for (int o = 16; o; o >>= 1) {
            float ov = __shfl_xor_sync(~0u, wv, o);
            int   oi = __shfl_xor_sync(~0u, wi, o);
            if (better(ov, oi, wv, wi)) { wv = ov; wi = oi; }
        }
        rv[s5] = wv; ri[s5] = wi;
        if (hp < 5 && wi == bi && wv == bv) hp++;
    }
}
#define MMA16(c, A, b0, b1) \
    asm volatile("mma.sync.aligned.m16n8k16.row.col.f32.f16.f16.f32 " \
        "{%0,%1,%2,%3},{%4,%5,%6,%7},{%8,%9},{%0,%1,%2,%3};" \
        : "+f"((c)[0]), "+f"((c)[1]), "+f"((c)[2]), "+f"((c)[3]) \
        : "r"((A).x), "r"((A).y), "r"((A).z), "r"((A).w), "r"(b0), "r"(b1))

// ---------------- device state ----------------
__device__ float g_hn[2][GG*HH];
__device__ float g_gp[12][GG*G3];
__device__ __align__(16) uint4 g_pah[NVT*1024];
__device__ __align__(16) uint4 g_pal[NVT*1024];
__device__ __align__(16) uint2 g_pbh[NT*32*32];
__device__ __align__(16) uint2 g_pbl[NT*32*32];
__device__ __align__(16) float g_out_all[(size_t)TT*GG*VV];
__device__ float g_pm[NB*GG];
__device__ float g_ps[NB*GG];
__device__ float g_pv[NB*GG*5];
__device__ int   g_pi[NB*GG*5];
__device__ float g_tv[GG][5];
__device__ int   g_ti[GG][5];
__device__ float g_mx[GG];
__device__ float g_ls[GG];
__device__ int   g_org_all[TT*BB*KK];
__device__ int   g_tok_all[TT*BB*KK];
__device__ int   g_bt_slot[BB*KK*TT];
__device__ int   g_bt_tok [BB*KK*TT];
__device__ int   g_cnt = 0;
__device__ int   g_gen = 0;

__device__ __forceinline__ void gbar() {
    __syncthreads();
    if (threadIdx.x == 0) {
        volatile int* vg = &g_gen;
        int gen = *vg;
        __threadfence();
        if (atomicAdd(&g_cnt, 1) == NB - 1) {
            g_cnt = 0;
            __threadfence();
            *vg = gen + 1;
        } else {
            while (*vg == gen) { }
        }
    }
    __syncthreads();
}

// ---------------- weight fp16-split fragment prep (once) ----------------
__global__ void k_prep(const float* __restrict__ lw) {
    int idx = blockIdx.x*256 + threadIdx.x;
    if (idx >= NVT*1024) return;
    int lane = idx & 31, ks = (idx >> 5) & 31, vt = idx >> 10;
    int m0 = vt*16 + (lane >> 2), m1 = m0 + 8;
    int k0 = ks*16 + (lane & 3)*2;
    const float* r0 = &lw[(size_t)m0*HH];
    const float* r1 = &lw[(size_t)m1*HH];
    float w[8] = { r0[k0], r0[k0+1], r1[k0], r1[k0+1],
                   r0[k0+8], r0[k0+9], r1[k0+8], r1[k0+9] };
    uint32_t hi[4], lo[4];
    #pragma unroll
    for (int p = 0; p < 4; p++) {
        __half h0 = __float2half_rn(w[p*2]),   h1 = __float2half_rn(w[p*2+1]);
        __half l0 = __float2half_rn((w[p*2]   - __half2float(h0)) * 2048.f);
        __half l1 = __float2half_rn((w[p*2+1] - __half2float(h1)) * 2048.f);
        hi[p] = (uint32_t)__half_as_ushort(h0) | ((uint32_t)__half_as_ushort(h1) << 16);
        lo[p] = (uint32_t)__half_as_ushort(l0) | ((uint32_t)__half_as_ushort(l1) << 16);
    }
    g_pah[idx] = make_uint4(hi[0], hi[1], hi[2], hi[3]);
    g_pal[idx] = make_uint4(lo[0], lo[1], lo[2], lo[3]);
}

// ---------------- the persistent kernel ----------------
__global__ void __launch_bounds__(NTH)
k_main(const float* __restrict__ attrs, const int* __restrict__ bos,
       const float* __restrict__ emb,
       const float* __restrict__ w_ih, const float* __restrict__ b_ih,
       const float* __restrict__ w_hh, const float* __restrict__ b_hh,
       const float* __restrict__ tw,   const float* __restrict__ tb,
       const float* __restrict__ lb) {
    union USm {
        struct { float wt[64][129]; float it[GG*64]; } p0;
        float smd[GG*268];
        float attrs_s[AA];
    };
    __shared__ USm u;
    __shared__ float s_bp[GG];
    __shared__ int   s_org[GG], s_tok[GG];

    const int bx = blockIdx.x, tid = threadIdx.x;
    const int warp = tid >> 5, lane = tid & 31;

    // init h0 (blocks 0..7) + per-block beam state
    if (bx < BB) {
        int b = bx;
        for (int i = tid; i < AA; i += NTH) u.attrs_s[i] = attrs[b*AA + i];
        __syncthreads();
        for (int j = tid; j < HH; j += NTH) {
            const float* wr = &tw[(size_t)j*AA];
            float acc = 0.f;
            for (int a = 0; a < AA; a++) acc += u.attrs_s[a] * wr[a];
            acc += tb[j];
            for (int k = 0; k < KK; k++) g_hn[0][(k*BB + b)*HH + j] = acc;
        }
    }
    if (tid < GG) {
        s_bp[tid]  = (tid < BB) ? 0.f : NEGF;
        s_org[tid] = tid / BB;
        s_tok[tid] = bos[0];
    }
    gbar();

    for (int t = 0; t < TT; t++) {
        const int prev = t & 1, cur = prev ^ 1;

        // ===== P0: GRU gate GEMM partials (144 items) =====
        for (int it = bx; it < 144; it += NB) {
            int mode = (it < 48) ? 0 : 1;
            int r = (it < 48) ? it : it - 48;
            int c = r / 12, jt = r % 12;
            const int KIN = mode ? HH : EE;
            const float* __restrict__ W = mode ? w_hh : w_ih;
            const int slot = mode ? 4 + c : c;
            const int j0 = jt * 128, kk0 = c * 64;
            for (int idx = tid; idx < 128*16; idx += NTH) {
                int jl = idx >> 4, q = idx & 15;
                float4 w4 = *reinterpret_cast<const float4*>(&W[(size_t)(j0+jl)*KIN + kk0 + q*4]);
                u.p0.wt[q*4+0][jl] = w4.x; u.p0.wt[q*4+1][jl] = w4.y;
                u.p0.wt[q*4+2][jl] = w4.z; u.p0.wt[q*4+3][jl] = w4.w;
            }
            for (int idx = tid; idx < GG*16; idx += NTH) {
                int g = idx >> 4, q = idx & 15;
                const float* src;
                if (mode == 0) src = &emb[(size_t)s_tok[g]*EE];
                else { int b = g % BB; src = &g_hn[prev][(s_org[g]*BB + b)*HH]; }
                *reinterpret_cast<float4*>(&u.p0.it[g*64 + q*4]) =
                    *reinterpret_cast<const float4*>(&src[kk0 + q*4]);
            }
            __syncthreads();
            {
                int ty = warp & 7, ci0 = (warp >> 3) * 2;
                float acc[2][5] = {};
                for (int kk = 0; kk < 64; kk++) {
                    float wv0 = u.p0.wt[kk][ci0*32 + lane];
                    float wv1 = u.p0.wt[kk][(ci0+1)*32 + lane];
                    #pragma unroll
                    for (int rr = 0; rr < 5; rr++) {
                        float xv = u.p0.it[(ty + 8*rr)*64 + kk];
                        acc[0][rr] += wv0 * xv;
                        acc[1][rr] += wv1 * xv;
                    }
                }
                #pragma unroll
                for (int rr = 0; rr < 5; rr++) {
                    int g = ty + 8*rr;
                    g_gp[slot][g*G3 + j0 + ci0*32 + lane]     = acc[0][rr];
                    g_gp[slot][g*G3 + j0 + (ci0+1)*32 + lane] = acc[1][rr];
                }
            }
            __syncthreads();
        }
        gbar();

        // ===== P1: gates + hn + B fragment pack =====
        {
            int gid = bx*NTH + tid;
            if (gid < GG*HH) {
                int g = gid >> 9, j = gid & 511, b = g % BB;
                float gi0 = b_ih[j], gi1 = b_ih[HH+j], gi2 = b_ih[2*HH+j];
                float gh0 = b_hh[j], gh1 = b_hh[HH+j], gh2 = b_hh[2*HH+j];
                #pragma unroll
                for (int c = 0; c < 4; c++) {
                    const float* p = &g_gp[c][g*G3];
                    gi0 += p[j]; gi1 += p[HH+j]; gi2 += p[2*HH+j];
                }
                #pragma unroll
                for (int c = 4; c < 12; c++) {
                    const float* p = &g_gp[c][g*G3];
                    gh0 += p[j]; gh1 += p[HH+j]; gh2 += p[2*HH+j];
                }
                float hprev = g_hn[prev][(s_org[g]*BB + b)*HH + j];
                float rg = 1.f / (1.f + expf(-(gi0 + gh0)));
                float zg = 1.f / (1.f + expf(-(gi1 + gh1)));
                float ng = tanhf(gi2 + rg*gh2);
                float hv = (1.f - zg)*ng + zg*hprev;
                g_hn[cur][g*HH + j] = hv;

                int nt = g >> 3, gr = g & 7;
                int ks = j >> 4, rr = j & 15;
                int reg = rr >> 3, i4 = (rr & 7) >> 1, hb = rr & 1;
                int ln = gr*4 + i4;
                int hidx = (((nt*32 + ks)*32 + ln)*2 + reg)*2 + hb;
                __half bh = __float2half_rn(hv);
                __half bl = __float2half_rn((hv - __half2float(bh)) * 2048.f);
                reinterpret_cast<__half*>(g_pbh)[hidx] = bh;
                reinterpret_cast<__half*>(g_pbl)[hidx] = bl;
            }
        }
        gbar();

        // ===== P2: vocab MMA + fused partial stats =====
        {
            const int item = bx, v0 = item * 256;
            const int vt = item*16 + warp;
            const uint4* pAh = &g_pah[(size_t)vt*1024 + lane];
            const uint4* pAl = &g_pal[(size_t)vt*1024 + lane];
            const uint2* pBh = &g_pbh[lane];
            const uint2* pBl = &g_pbl[lane];
            float a1[NT][4] = {}, a2[NT][4] = {};
            #pragma unroll 2
            for (int ks = 0; ks < 32; ks++) {
                uint4 Ah = pAh[ks*32];
                uint4 Al = pAl[ks*32];
                #pragma unroll
                for (int nt = 0; nt < NT; nt++) {
                    uint2 bh = pBh[(nt*32 + ks)*32];
                    uint2 bl = pBl[(nt*32 + ks)*32];
                    MMA16(a1[nt], Ah, bh.x, bh.y);
                    MMA16(a2[nt], Ah, bl.x, bl.y);
                    MMA16(a2[nt], Al, bh.x, bh.y);
                }
            }
            #pragma unroll
            for (int nt = 0; nt < NT; nt++) {
                #pragma unroll
                for (int c = 0; c < 4; c++) {
                    float val = a1[nt][c] + a2[nt][c] * (1.f/2048.f);
                    int g = nt*8 + (lane & 3)*2 + (c & 1);
                    int vloc = warp*16 + (lane >> 2) + 8*(c >> 1);
                    u.smd[g*268 + vloc] = val;
                }
            }
            __syncthreads();
            for (int g = warp; g < GG; g += 16) {
                const float4* rp = reinterpret_cast<const float4*>(&u.smd[g*268]);
                float4 x0 = rp[lane], x1 = rp[lane + 32];
                float4 b0 = *reinterpret_cast<const float4*>(&lb[v0 + lane*4]);
                float4 b1 = *reinterpret_cast<const float4*>(&lb[v0 + 128 + lane*4]);
                x0.x += b0.x; x0.y += b0.y; x0.z += b0.z; x0.w += b0.w;
                x1.x += b1.x; x1.y += b1.y; x1.z += b1.z; x1.w += b1.w;
                float* dst = &g_out_all[((size_t)t*GG + g)*VV + v0];
                *reinterpret_cast<float4*>(dst + lane*4)       = x0;
                *reinterpret_cast<float4*>(dst + 128 + lane*4) = x1;

                float vv[8] = {x0.x, x0.y, x0.z, x0.w, x1.x, x1.y, x1.z, x1.w};
                float m = vv[0];
                #pragma unroll
                for (int i = 1; i < 8; i++) m = fmaxf(m, vv[i]);
                for (int o = 16; o; o >>= 1) m = fmaxf(m, __shfl_xor_sync(~0u, m, o));
                float s = 0.f;
                #pragma unroll
                for (int i = 0; i < 8; i++) s += expf(vv[i] - m);
                for (int o = 16; o; o >>= 1) s += __shfl_xor_sync(~0u, s, o);
                float t5[5]; int i5[5];
                #pragma unroll
                for (int i = 0; i < 5; i++) { t5[i] = -1e38f; i5[i] = 0x7fffffff; }
                #pragma unroll
                for (int i = 0; i < 4; i++) ins5(t5, i5, vv[i], v0 + lane*4 + i);
                #pragma unroll
                for (int i = 0; i < 4; i++) ins5(t5, i5, vv[4+i], v0 + 128 + lane*4 + i);
                float rv[5]; int ri[5];
                warp_top5(t5, i5, rv, ri);
                if (lane == 0) {
                    g_pm[item*GG + g] = m;
                    g_ps[item*GG + g] = s;
                    #pragma unroll
                    for (int q = 0; q < 5; q++) {
                        g_pv[(item*GG + g)*5 + q] = rv[q];
                        g_pi[(item*GG + g)*5 + q] = ri[q];
                    }
                }
            }
            __syncthreads();
        }
        gbar();

        // ===== P3: cross-block reduce (40 warps) =====
        if (bx < 5 && warp < 8) {
            int g = bx*8 + warp;
            float m = -1e38f;
            for (int p = lane; p < NB; p += 32) m = fmaxf(m, g_pm[p*GG + g]);
            for (int o = 16; o; o >>= 1) m = fmaxf(m, __shfl_xor_sync(~0u, m, o));
            float s = 0.f;
            float t5[5]; int i5[5];
            #pragma unroll
            for (int i = 0; i < 5; i++) { t5[i] = -1e38f; i5[i] = 0x7fffffff; }
            for (int p = lane; p < NB; p += 32) {
                s += g_ps[p*GG + g] * expf(g_pm[p*GG + g] - m);
                #pragma unroll
                for (int q = 0; q < 5; q++)
                    ins5(t5, i5, g_pv[(p*GG + g)*5 + q], g_pi[(p*GG + g)*5 + q]);
            }
            for (int o = 16; o; o >>= 1) s += __shfl_xor_sync(~0u, s, o);
            float rv[5]; int ri[5];
            warp_top5(t5, i5, rv, ri);
            if (lane == 0) {
                #pragma unroll
                for (int q = 0; q < 5; q++) { g_tv[g][q] = rv[q]; g_ti[g][q] = ri[q]; }
                g_mx[g] = m;
                g_ls[g] = logf(s);
            }
        }
        gbar();

        // ===== combine (every block redundantly, identical arithmetic) =====
        if (tid < BB) {
            int b = tid;
            float cv[KK*KK]; int ct[KK*KK];
            #pragma unroll
            for (int ko = 0; ko < KK; ko++) {
                int gg = ko*BB + b;
                float Mg = g_mx[gg], Lg = g_ls[gg], bpv = s_bp[gg];
                #pragma unroll
                for (int q = 0; q < KK; q++) {
                    cv[ko*KK + q] = bpv + ((g_tv[gg][q] - Mg) - Lg);
                    ct[ko*KK + q] = g_ti[gg][q];
                }
            }
            float nbp[KK]; int norg[KK], ntok[KK];
            bool used[KK*KK] = {};
            #pragma unroll
            for (int kn = 0; kn < KK; kn++) {
                int bf = -1; float bv = 0.f;
                for (int f = 0; f < KK*KK; f++)
                    if (!used[f] && (bf < 0 || cv[f] > bv)) { bv = cv[f]; bf = f; }
                used[bf] = true;
                nbp[kn] = bv; norg[kn] = bf / KK; ntok[kn] = ct[bf];
            }
            #pragma unroll
            for (int kn = 0; kn < KK; kn++) {
                s_bp[kn*BB + b]  = nbp[kn];
                s_org[kn*BB + b] = norg[kn];
                s_tok[kn*BB + b] = ntok[kn];
                if (bx == 0) {
                    g_org_all[t*BB*KK + b*KK + kn] = norg[kn];
                    g_tok_all[t*BB*KK + b*KK + kn] = ntok[kn];
                }
            }
        }
        __syncthreads();
    }
}

// ---------------- backtrack + final write ----------------
__global__ void k_backtrack() {
    int i = threadIdx.x;
    if (i >= BB*KK) return;
    int b = i / KK, k = i % KK, idx = k;
    for (int t = TT - 1; t >= 0; t--) {
        int o = g_org_all[t*BB*KK + b*KK + idx];
        g_bt_slot[(b*KK + k)*TT + t] = o;
        g_bt_tok [(b*KK + k)*TT + t] = g_tok_all[t*BB*KK + b*KK + idx];
        idx = o;
    }
}

__global__ void k_write(float* __restrict__ out) {
    int q = blockIdx.x;
    int b = q / (KK*TT), rem = q % (KK*TT);
    int k = rem / TT, t = rem % TT;
    int s = g_bt_slot[(b*KK + k)*TT + t];
    int tok = g_bt_tok[(b*KK + k)*TT + t];
    const float4* src = (const float4*)&g_out_all[((size_t)t*GG + (s*BB + b))*VV];
    size_t N = (size_t)BB*KK*TT*VV;
    size_t off = (((size_t)b*KK + k)*TT + t)*(size_t)VV;
    float4* d0 = (float4*)(out + off);
    float4* d1 = (float4*)(out + N + off);
    float4* d2 = (float4*)(out + 2*N + off);
    for (int i = threadIdx.x; i < VV/4; i += blockDim.x) {
        d0[i] = src[i];
        int vb = i*4;
        float4 h;
        h.x = (vb == tok) ? 1.f : 0.f;  h.y = (vb+1 == tok) ? 1.f : 0.f;
        h.z = (vb+2 == tok) ? 1.f : 0.f; h.w = (vb+3 == tok) ? 1.f : 0.f;
        d1[i] = h; d2[i] = h;
    }
}

// ---------------- launch ----------------
extern "C" void kernel_launch(void* const* d_in, const int* in_sizes, int n_in,
                              void* d_out, int out_size) {
    const float* attrs = (const float*)d_in[0];
    const int*   bos   = (const int*)  d_in[1];
    const float* emb   = (const float*)d_in[4];
    const float* w_ih  = (const float*)d_in[5];
    const float* b_ih  = (const float*)d_in[6];
    const float* w_hh  = (const float*)d_in[7];
    const float* b_hh  = (const float*)d_in[8];
    const float* tw    = (const float*)d_in[9];
    const float* tb    = (const float*)d_in[10];
    const float* lw    = (const float*)d_in[11];
    const float* lb    = (const float*)d_in[12];
    float* out = (float*)d_out;

    k_prep<<<(NVT*1024 + 255)/256, 256>>>(lw);
    k_main<<<NB, NTH>>>(attrs, bos, emb, w_ih, b_ih, w_hh, b_hh, tw, tb, lb);
    k_backtrack<<<1, 64>>>();
    k_write<<<BB*KK*TT, 256>>>(out);
}